// round 10
// baseline (speedup 1.0000x reference)
#include <cuda_runtime.h>
#include <math.h>
#include <mma.h>

using namespace nvcuda;

#define FULLMASK 0xffffffffu

#define BB 8
#define SS 1024
#define EE 512
#define HH 8
#define DD 64

// ---------------- scratch (device globals: allocation-free) ----------------
__device__ float g_qh[BB * HH * SS * DD];   // [b][h][s][d]
__device__ float g_kh[BB * HH * SS * DD];
__device__ float g_vh[BB * HH * SS * DD];
__device__ float g_ao[BB * SS * EE];        // attention output, [b][s][h*64+d]

// ---------------- tf32 WMMA projection: dst = A @ W^T + bias ---------------
#define ALD 36   // A tile leading dim (128x32 + pad)
#define BLD 68   // B tile leading dim (32x64 + pad)
#define CLD 68   // C stage leading dim

__global__ __launch_bounds__(256, 2)
void proj_tf32(const float* __restrict__ A_param, const float* __restrict__ A2_param,
               const float* __restrict__ W, const float* __restrict__ bias,
               float* __restrict__ C_param, int mode)
{
    __shared__ __align__(16) float smem[128 * CLD];   // max(As+Bs, Cs)
    float* As = smem;                                  // [128][ALD]
    float* Bs = smem + 128 * ALD;                      // [32][BLD]
    float* Cs = smem;                                  // [128][CLD] (epilogue)

    int bxm = blockIdx.x;
    const float* A;
    float* dst = nullptr;
    if (mode == 0) {
        if (bxm < 64) { A = A_param; dst = g_qh; }
        else          { A = A2_param; dst = g_kh; bxm -= 64; }
    } else if (mode == 2) {
        A = A_param; dst = g_vh;
    } else {
        A = (const float*)g_ao;
    }

    const int tid = threadIdx.x;
    const int w = tid >> 5;
    const int wm = w >> 1;
    const int wn = w & 1;
    const int m0 = bxm * 128;
    const int n0 = blockIdx.y * 64;

    wmma::fragment<wmma::accumulator, 16, 16, 8, float> acc[2][2];
#pragma unroll
    for (int i = 0; i < 2; i++)
#pragma unroll
        for (int j = 0; j < 2; j++) wmma::fill_fragment(acc[i][j], 0.f);

    for (int k0 = 0; k0 < 512; k0 += 32) {
        __syncthreads();
#pragma unroll
        for (int i = 0; i < 4; i++) {                 // A: 128x32
            const int fi = tid + i * 256;
            const int r = fi >> 3, c4 = (fi & 7) << 2;
            *(float4*)&As[r * ALD + c4] =
                *(const float4*)&A[(m0 + r) * 512 + k0 + c4];
        }
#pragma unroll
        for (int i = 0; i < 2; i++) {                 // B: W[n][k] -> Bs[k][n]
            const int fi = tid + i * 256;
            const int n = fi >> 3, k4 = (fi & 7) << 2;
            const float4 w4 = *(const float4*)&W[(n0 + n) * 512 + k0 + k4];
            Bs[(k4 + 0) * BLD + n] = w4.x;
            Bs[(k4 + 1) * BLD + n] = w4.y;
            Bs[(k4 + 2) * BLD + n] = w4.z;
            Bs[(k4 + 3) * BLD + n] = w4.w;
        }
        __syncthreads();

#pragma unroll
        for (int ks = 0; ks < 4; ks++) {
            wmma::fragment<wmma::matrix_a, 16, 16, 8, wmma::precision::tf32, wmma::row_major> fa[2];
            wmma::fragment<wmma::matrix_b, 16, 16, 8, wmma::precision::tf32, wmma::row_major> fb[2];
#pragma unroll
            for (int i = 0; i < 2; i++) {
                wmma::load_matrix_sync(fa[i], &As[(wm * 32 + i * 16) * ALD + ks * 8], ALD);
#pragma unroll
                for (int t = 0; t < fa[i].num_elements; t++)
                    fa[i].x[t] = wmma::__float_to_tf32(fa[i].x[t]);
            }
#pragma unroll
            for (int j = 0; j < 2; j++) {
                wmma::load_matrix_sync(fb[j], &Bs[(ks * 8) * BLD + wn * 32 + j * 16], BLD);
#pragma unroll
                for (int t = 0; t < fb[j].num_elements; t++)
                    fb[j].x[t] = wmma::__float_to_tf32(fb[j].x[t]);
            }
#pragma unroll
            for (int i = 0; i < 2; i++)
#pragma unroll
                for (int j = 0; j < 2; j++)
                    wmma::mma_sync(acc[i][j], fa[i], fb[j], acc[i][j]);
        }
    }

    __syncthreads();
#pragma unroll
    for (int i = 0; i < 2; i++)
#pragma unroll
        for (int j = 0; j < 2; j++)
            wmma::store_matrix_sync(&Cs[(wm * 32 + i * 16) * CLD + wn * 32 + j * 16],
                                    acc[i][j], CLD, wmma::mem_row_major);
    __syncthreads();

    if (mode == 3) {
#pragma unroll
        for (int i = 0; i < 8; i++) {
            const int fi = tid + i * 256;
            const int r = fi >> 4, c4 = (fi & 15) << 2;
            const int m = m0 + r;
            float4 o;
            o.x = Cs[r * CLD + c4 + 0] + bias[n0 + c4 + 0];
            o.y = Cs[r * CLD + c4 + 1] + bias[n0 + c4 + 1];
            o.z = Cs[r * CLD + c4 + 2] + bias[n0 + c4 + 2];
            o.w = Cs[r * CLD + c4 + 3] + bias[n0 + c4 + 3];
            *(float4*)&C_param[m * 512 + n0 + c4] = o;
        }
    } else {
        const int hh = n0 >> 6;
#pragma unroll
        for (int i = 0; i < 8; i++) {
            const int fi = tid + i * 256;
            const int r = fi >> 4, c4 = (fi & 15) << 2;
            const int m = m0 + r;
            const int b = m >> 10, s = m & 1023;
            float4 o;
            o.x = Cs[r * CLD + c4 + 0] + bias[n0 + c4 + 0];
            o.y = Cs[r * CLD + c4 + 1] + bias[n0 + c4 + 1];
            o.z = Cs[r * CLD + c4 + 2] + bias[n0 + c4 + 2];
            o.w = Cs[r * CLD + c4 + 3] + bias[n0 + c4 + 3];
            *(float4*)&dst[(((b << 3) + hh) * 1024 + s) * 64 + c4] = o;
        }
    }
}

// ---------------- fused decay-attention ------------------------------------
__device__ __forceinline__ float wredmax(float v) {
#pragma unroll
    for (int o = 16; o; o >>= 1) v = fmaxf(v, __shfl_xor_sync(FULLMASK, v, o));
    return v;
}
__device__ __forceinline__ float wredsum(float v) {
#pragma unroll
    for (int o = 16; o; o >>= 1) v += __shfl_xor_sync(FULLMASK, v, o);
    return v;
}

// FMA-pipe exp for x <= 0 (no MUFU). exp(x) = 2^(x*log2e); deg-5 Taylor for
// 2^f on [-0.5, 0.5] (rel err ~2.4e-6), exponent via integer add (clamped so
// deep-negative args underflow to ~0 instead of wrapping).
__device__ __forceinline__ float fexp_neg(float x) {
    const float t = x * 1.4426950408889634f;
    const float n = rintf(t);
    const float f = t - n;
    float p = 1.3333558e-3f;               // ln2^5/120
    p = fmaf(p, f, 9.6181291e-3f);         // ln2^4/24
    p = fmaf(p, f, 5.5504109e-2f);         // ln2^3/6
    p = fmaf(p, f, 2.4022651e-1f);         // ln2^2/2
    p = fmaf(p, f, 6.9314718e-1f);         // ln2
    p = fmaf(p, f, 1.0f);
    int e = (int)n;
    e = (e < -126) ? -126 : e;             // underflow -> denormal/0
    return __int_as_float(__float_as_int(p) + (e << 23));
}

// softmax -> cumsum decay -> rescaled softmax, entirely in registers.
// j-map: j = (c>>2)*128 + (c&3)*32 + lane; chunk min-j is MONOTONE in c, so
// all passes stop at ncap = min(nreg, (i>>5)+1) — the exact causal triangle.
__device__ __forceinline__ void row_decay_softmax(float (&s)[32], const int i,
                                                  const int nreg, const int lane,
                                                  const float gamma)
{
    const int ncap0 = (i >> 5) + 1;
    const int ncap = (nreg < ncap0) ? nreg : ncap0;

    float m1 = -3.0e38f;
#pragma unroll
    for (int c = 0; c < 32; c++) if (c < ncap) {
        const int j = (c >> 2) * 128 + (c & 3) * 32 + lane;
        s[c] *= 0.125f;                              // 1/sqrt(64)
        if (j <= i) m1 = fmaxf(m1, s[c]);
    }
    m1 = wredmax(m1);

    // scan pass over unnormalized p = exp(s - m1); cum[] inclusive, carry -> Z
    float cum[32];
    float carry = 0.f;
#pragma unroll
    for (int c = 0; c < 32; c++) if (c < ncap) {
        const int j = (c >> 2) * 128 + (c & 3) * 32 + lane;
        float v = (j <= i) ? fexp_neg(s[c] - m1) : 0.f;
#pragma unroll
        for (int o = 1; o < 32; o <<= 1) {
            const float n = __shfl_up_sync(FULLMASK, v, o);
            if (lane >= o) v += n;
        }
        cum[c] = carry + v;
        carry = __shfl_sync(FULLMASK, cum[c], 31);
    }
    const float invZ = 1.f / carry;                  // Z == final carry

    // decay pass (fused m2 tracking); sqrt via single MUFU.RSQ
    float m2 = -3.0e38f;
#pragma unroll
    for (int c = 0; c < 32; c++) if (c < ncap) {
        const int j = (c >> 2) * 128 + (c & 3) * 32 + lane;
        float x = fmaxf((1.f - cum[c] * invZ) * (float)(i - j), 0.f);
        const float sq = (x > 0.f) ? x * rsqrtf(x) : 0.f;
        float eff = fexp_neg(sq * gamma);
        eff = fmaxf(eff, 1e-5f);                     // clip (upper 1e5 unreachable: eff<=1)
        s[c] *= eff;
        if (j <= i) m2 = fmaxf(m2, s[c]);
    }
    m2 = wredmax(m2);

    float Z2 = 0.f;
#pragma unroll
    for (int c = 0; c < 32; c++) {
        if (c < ncap) {
            const int j = (c >> 2) * 128 + (c & 3) * 32 + lane;
            s[c] = (j <= i) ? fexp_neg(s[c] - m2) : 0.f;
            Z2 += s[c];
        } else s[c] = 0.f;
    }
    Z2 = wredsum(Z2);
    const float psc = (i == 0) ? 0.f : (1.f / Z2);   // zero_pad first query row
#pragma unroll
    for (int c = 0; c < 32; c++) s[c] *= psc;
}

#define KV_LD 68     // padded leading dim for K/V tile
#define ST_LD 136    // padded leading dim for stage buffer

// grid (64, H, B), 256 threads: 8 warps, block covers 16 query rows.
__global__ __launch_bounds__(256, 2)
void attn_kernel(const float* __restrict__ gammas)
{
    const int tid = threadIdx.x, lane = tid & 31, w = tid >> 5;
    const int bx = blockIdx.x, h = blockIdx.y, b = blockIdx.z;
    const int r0 = bx * 16 + 2 * w;
    const int r1 = r0 + 1;
    const int ntiles = (bx * 16 + 143) >> 7;
    const int bh = (b * 8 + h) * (1024 * 64);
    const float* qb = g_qh + bh;
    const float* kb = g_kh + bh;
    const float* vb = g_vh + bh;

    __shared__ float Qs[16][KV_LD];
    __shared__ float KVs[128][KV_LD];
    __shared__ float Stg[16 * ST_LD];

    {
        const int r = tid >> 4, d4 = (tid & 15) << 2;
        const float4 qv = *(const float4*)&qb[(bx * 16 + r) * 64 + d4];
        Qs[r][d4] = qv.x; Qs[r][d4 + 1] = qv.y;
        Qs[r][d4 + 2] = qv.z; Qs[r][d4 + 3] = qv.w;
    }

    const float gx = gammas[h];
    const float gamma = -((gx > 20.f) ? gx : log1pf(expf(gx)));

    float s0[32], s1[32];

    // ---- Phase 1: scores C[16 x 128] per tile via tf32 wmma ----
    for (int kt = 0; kt < ntiles; kt++) {
        __syncthreads();
#pragma unroll
        for (int r = 0; r < 8; r++) {
            const int fi = tid + r * 256;
            const int jj = fi >> 4, d4 = (fi & 15) << 2;
            const float4 t4 = *(const float4*)&kb[(kt * 128 + jj) * 64 + d4];
            KVs[jj][d4] = t4.x; KVs[jj][d4 + 1] = t4.y;
            KVs[jj][d4 + 2] = t4.z; KVs[jj][d4 + 3] = t4.w;
        }
        __syncthreads();

        wmma::fragment<wmma::accumulator, 16, 16, 8, float> fc;
        wmma::fill_fragment(fc, 0.f);
#pragma unroll
        for (int kk = 0; kk < 8; kk++) {
            wmma::fragment<wmma::matrix_a, 16, 16, 8, wmma::precision::tf32, wmma::row_major> fa;
            wmma::fragment<wmma::matrix_b, 16, 16, 8, wmma::precision::tf32, wmma::col_major> fb;
            wmma::load_matrix_sync(fa, &Qs[0][kk * 8], KV_LD);
            wmma::load_matrix_sync(fb, &KVs[w * 16][kk * 8], KV_LD);
#pragma unroll
            for (int t = 0; t < fa.num_elements; t++) fa.x[t] = wmma::__float_to_tf32(fa.x[t]);
#pragma unroll
            for (int t = 0; t < fb.num_elements; t++) fb.x[t] = wmma::__float_to_tf32(fb.x[t]);
            wmma::mma_sync(fc, fa, fb, fc);
        }
        wmma::store_matrix_sync(&Stg[w * 16], fc, ST_LD, wmma::mem_row_major);
        __syncthreads();

#pragma unroll
        for (int t = 0; t < 4; t++) {
            s0[kt * 4 + t] = Stg[(2 * w) * ST_LD + t * 32 + lane];
            s1[kt * 4 + t] = Stg[(2 * w + 1) * ST_LD + t * 32 + lane];
        }
    }

    // ---- Phase 2: per-row softmax/decay/softmax ----
    const int nreg = ntiles * 4;
    row_decay_softmax(s0, r0, nreg, lane, gamma);
    row_decay_softmax(s1, r1, nreg, lane, gamma);

    // ---- Phase 3: O[16 x 64] = P @ V via tf32 wmma ----
    const int n0 = (w & 3) * 16;
    const int khalf = w >> 2;
    wmma::fragment<wmma::accumulator, 16, 16, 8, float> facc;
    wmma::fill_fragment(facc, 0.f);

    for (int kt = 0; kt < ntiles; kt++) {
        __syncthreads();
#pragma unroll
        for (int t = 0; t < 4; t++) {
            Stg[(2 * w) * ST_LD + t * 32 + lane]     = s0[kt * 4 + t];
            Stg[(2 * w + 1) * ST_LD + t * 32 + lane] = s1[kt * 4 + t];
        }
#pragma unroll
        for (int r = 0; r < 8; r++) {
            const int fi = tid + r * 256;
            const int jj = fi >> 4, d4 = (fi & 15) << 2;
            const float4 t4 = *(const float4*)&vb[(kt * 128 + jj) * 64 + d4];
            KVs[jj][d4] = t4.x; KVs[jj][d4 + 1] = t4.y;
            KVs[jj][d4 + 2] = t4.z; KVs[jj][d4 + 3] = t4.w;
        }
        __syncthreads();

#pragma unroll
        for (int kk = 0; kk < 8; kk++) {
            const int k0 = khalf * 64 + kk * 8;
            wmma::fragment<wmma::matrix_a, 16, 16, 8, wmma::precision::tf32, wmma::row_major> pa;
            wmma::fragment<wmma::matrix_b, 16, 16, 8, wmma::precision::tf32, wmma::row_major> vbf;
            wmma::load_matrix_sync(pa, &Stg[k0], ST_LD);
            wmma::load_matrix_sync(vbf, &KVs[k0][n0], KV_LD);
#pragma unroll
            for (int t = 0; t < pa.num_elements; t++) pa.x[t] = wmma::__float_to_tf32(pa.x[t]);
#pragma unroll
            for (int t = 0; t < vbf.num_elements; t++) vbf.x[t] = wmma::__float_to_tf32(vbf.x[t]);
            wmma::mma_sync(facc, pa, vbf, facc);
        }
    }

    __syncthreads();
    wmma::store_matrix_sync(&Stg[khalf * 1024 + n0], facc, 64, wmma::mem_row_major);
    __syncthreads();

    {
        const int row = tid >> 4, d4 = (tid & 15) << 2;
        float4 o;
        o.x = Stg[row * 64 + d4]     + Stg[1024 + row * 64 + d4];
        o.y = Stg[row * 64 + d4 + 1] + Stg[1024 + row * 64 + d4 + 1];
        o.z = Stg[row * 64 + d4 + 2] + Stg[1024 + row * 64 + d4 + 2];
        o.w = Stg[row * 64 + d4 + 3] + Stg[1024 + row * 64 + d4 + 3];
        *(float4*)&g_ao[(b * 1024 + bx * 16 + row) * 512 + h * 64 + d4] = o;
    }
}

// ---------------- launch ----------------------------------------------------
extern "C" void kernel_launch(void* const* d_in, const int* in_sizes, int n_in,
                              void* d_out, int out_size)
{
    (void)in_sizes; (void)n_in; (void)out_size;
    const float* q  = (const float*)d_in[0];
    const float* k  = (const float*)d_in[1];
    const float* v  = (const float*)d_in[2];
    const float* Wk = (const float*)d_in[3];
    const float* bk = (const float*)d_in[4];
    const float* Wv = (const float*)d_in[5];
    const float* bv = (const float*)d_in[6];
    const float* Wo = (const float*)d_in[7];
    const float* bo = (const float*)d_in[8];
    const float* gm = (const float*)d_in[9];
    float* out = (float*)d_out;

    proj_tf32<<<dim3(128, 8), 256>>>(q, k, Wk, bk, nullptr, 0);      // q,k -> g_qh,g_kh
    proj_tf32<<<dim3(64, 8), 256>>>(v, nullptr, Wv, bv, nullptr, 2); // -> g_vh

    attn_kernel<<<dim3(64, 8, 8), 256>>>(gm);                        // -> g_ao

    proj_tf32<<<dim3(64, 8), 256>>>(nullptr, nullptr, Wo, bo, out, 3); // -> d_out
}